// round 11
// baseline (speedup 1.0000x reference)
#include <cuda_runtime.h>
#include <cuda_fp16.h>
#include <cstdint>

#define BROWS 4096
#define INF   1024
#define OUTF  1024
#define KDIM  9216          // INF * 9  (silu + 8 basis columns per input feature)

// GEMM config: persistent, 128x64 tiles, split-K=4, dynamic queue, 256 thr
#define TMd 128
#define TNd 64
#define KSPLIT 4
#define KPER  (KDIM / KSPLIT)   // 2304
#define CHUNK 64                // k-chunk in halfs
#define ITERSU (KPER / CHUNK)   // 36
#define STAGES 3
#define SROW_H 72               // smem row stride in halfs (144 B, conflict-free)
#define A_BYTES (TMd * SROW_H * 2)        // 18432
#define B_BYTES (TNd * SROW_H * 2)        // 9216
#define STAGE_BYTES (A_BYTES + B_BYTES)   // 27648
#define SMEM_TOTAL (STAGES * STAGE_BYTES + 16)  // 82960
#define NUNITS ((BROWS / TMd) * (OUTF / TNd) * KSPLIT)  // 2048
#define GCTAS 296
#define GTHREADS 256

// Scratch (static device globals — no runtime allocation)
__device__ __align__(256) __half g_act[(size_t)BROWS * KDIM];   // 75 MB
__device__ __align__(256) __half g_w[(size_t)OUTF * KDIM];      // 19 MB
__device__ __align__(256) float  g_part[(size_t)KSPLIT * BROWS * OUTF];  // 67 MB
__device__ int g_ctr;

#define LDSM4(r0, r1, r2, r3, addr)                                         \
    asm volatile("ldmatrix.sync.aligned.m8n8.x4.shared.b16 {%0,%1,%2,%3}, [%4];" \
                 : "=r"(r0), "=r"(r1), "=r"(r2), "=r"(r3) : "r"(addr))

// ---------------------------------------------------------------------------
// Kernel 1: activation matrix — closed-form uniform cubic B-spline.
// Act[b, i*9+0]=silu(x); only 4 basis cols (q=j-3..j) are nonzero.
// ---------------------------------------------------------------------------
#define ACT_EPT 8
__global__ __launch_bounds__(256) void act_kernel(const float* __restrict__ x,
                                                  const float* __restrict__ grid) {
    __shared__ __half sbuf[256 * ACT_EPT * 9];
    const int tid = threadIdx.x;
    const size_t base = (size_t)blockIdx.x * (256 * ACT_EPT);

    const float g0   = __ldg(grid);
    const float invh = 11.f / (__ldg(grid + 11) - g0);

    // zero-fill staging tile
    uint4 z; z.x = z.y = z.z = z.w = 0u;
#pragma unroll
    for (int i = 0; i < 9; i++) ((uint4*)sbuf)[tid + i * 256] = z;
    __syncthreads();

#pragma unroll
    for (int e = 0; e < ACT_EPT; e++) {
        const int loc = tid + e * 256;
        float xv = x[base + loc];

        float u = (xv - g0) * invh;
        float jf = floorf(u);
        int j = (int)jf;
        j = j < 0 ? 0 : (j > 10 ? 10 : j);
        float f = u - (float)j;
        float f2 = f * f, f3 = f2 * f;
        float om = 1.f - f;
        float p0 = f3 * (1.f / 6.f);                 // basis q = j
        float p3 = om * om * om * (1.f / 6.f);       // basis q = j-3
        float p2 = 0.5f * f3 - f2 + (4.f / 6.f);     // basis q = j-2
        float p1 = 1.f - p0 - p2 - p3;               // basis q = j-1

        float s = xv * __frcp_rn(1.f + __expf(-xv)); // silu

        __half* o = sbuf + loc * 9;
        o[0] = __float2half_rn(s);
        if (j < 8)               o[1 + j]     = __float2half_rn(p0);
        if (j >= 1 && j - 1 < 8) o[1 + j - 1] = __float2half_rn(p1);
        if (j >= 2 && j - 2 < 8) o[1 + j - 2] = __float2half_rn(p2);
        if (j >= 3 && j - 3 < 8) o[1 + j - 3] = __float2half_rn(p3);
    }
    __syncthreads();

    const uint4* s4 = (const uint4*)sbuf;            // 2304 x 16B
    uint4* g4 = (uint4*)(g_act + base * 9);
#pragma unroll
    for (int i = tid; i < 2304; i += 256) g4[i] = s4[i];
}

// ---------------------------------------------------------------------------
// Kernel 2: weight matrix.  W[o, i*9+0]=bw[o,i], [.. +1+q]=sw[o,i,q]
// ---------------------------------------------------------------------------
__global__ __launch_bounds__(256) void wconv_kernel(const float* __restrict__ bw,
                                                    const float* __restrict__ sw) {
    __shared__ __half sbuf[256 * 9];
    int tid = threadIdx.x;
    if (blockIdx.x == 0 && tid == 0) g_ctr = 0;   // reset GEMM work queue
    int idx = blockIdx.x * 256 + tid;   // o*1024 + i
    sbuf[tid * 9] = __float2half_rn(bw[idx]);
    const float4* sp = (const float4*)(sw + (size_t)idx * 8);
    float4 a = sp[0], b = sp[1];
    sbuf[tid * 9 + 1] = __float2half_rn(a.x); sbuf[tid * 9 + 2] = __float2half_rn(a.y);
    sbuf[tid * 9 + 3] = __float2half_rn(a.z); sbuf[tid * 9 + 4] = __float2half_rn(a.w);
    sbuf[tid * 9 + 5] = __float2half_rn(b.x); sbuf[tid * 9 + 6] = __float2half_rn(b.y);
    sbuf[tid * 9 + 7] = __float2half_rn(b.z); sbuf[tid * 9 + 8] = __float2half_rn(b.w);
    __syncthreads();

    const uint4* s4 = (const uint4*)sbuf;
    uint4* g4 = (uint4*)(g_w + (size_t)blockIdx.x * 2304);
#pragma unroll
    for (int i = tid; i < 288; i += 256) g4[i] = s4[i];
}

// ---------------------------------------------------------------------------
// Kernel 3: fp16 mma.sync GEMM, persistent split-K, ldmatrix operand loads.
// 296 CTAs (2/SM), 2048 units, 8 warps (4m x 2n), warp tile 32x32.
// ---------------------------------------------------------------------------
__device__ __forceinline__ void issue_stage(uint32_t sb, int stage, int it,
                                            int m0, int n0, int kb0, int tid) {
    const int kk = kb0 + it * CHUNK;
    const uint32_t sA = sb + stage * STAGE_BYTES;
    const uint32_t sB = sA + A_BYTES;
#pragma unroll
    for (int j = 0; j < 6; j++) {             // 192 rows x 8 chunks = 1536 copies
        int id  = tid + j * GTHREADS;         // 0..1535
        int row = id >> 3, c = id & 7;
        if (row < TMd) {
            const __half* ga = &g_act[(size_t)(m0 + row) * KDIM + kk + c * 8];
            asm volatile("cp.async.cg.shared.global [%0], [%1], 16;"
                         :: "r"(sA + (uint32_t)(row * SROW_H + c * 8) * 2), "l"(ga));
        } else {
            int r2 = row - TMd;
            const __half* gb = &g_w[(size_t)(n0 + r2) * KDIM + kk + c * 8];
            asm volatile("cp.async.cg.shared.global [%0], [%1], 16;"
                         :: "r"(sB + (uint32_t)(r2 * SROW_H + c * 8) * 2), "l"(gb));
        }
    }
}

__global__ __launch_bounds__(GTHREADS, 2) void gemm_kernel() {
    extern __shared__ __align__(16) char smem[];
    const uint32_t sb = (uint32_t)__cvta_generic_to_shared(smem);
    int* s_unit = (int*)(smem + STAGES * STAGE_BYTES);
    const int tid = threadIdx.x;
    const int wid = tid >> 5, lane = tid & 31;
    const int g = lane >> 2, t = lane & 3;
    const int wm = wid >> 1, wn = wid & 1;     // 4m x 2n warp grid, warp 32x32

    // ldmatrix per-lane tile offsets (PTX fragment tile order)
    const int arow = (((lane >> 3) & 1) << 3) + (lane & 7);
    const int acol = (lane >> 4) << 3;
    const int brow = ((lane >> 4) << 3) + (lane & 7);
    const int bcol = ((lane >> 3) & 1) << 3;

    for (;;) {
        if (tid == 0) *s_unit = atomicAdd(&g_ctr, 1);
        __syncthreads();
        const int u = *s_unit;
        if (u >= NUNITS) break;
        const int m0  = (u >> 6) * TMd;         // 16 consecutive units share A strip
        const int ks  = (u >> 4) & 3;
        const int n0  = (u & 15) * TNd;
        const int kb0 = ks * KPER;

        float acc[2][4][4];
#pragma unroll
        for (int i = 0; i < 2; i++)
#pragma unroll
            for (int jj = 0; jj < 4; jj++)
#pragma unroll
                for (int r = 0; r < 4; r++) acc[i][jj][r] = 0.f;

#pragma unroll
        for (int s = 0; s < STAGES - 1; s++) {
            issue_stage(sb, s, s, m0, n0, kb0, tid);
            asm volatile("cp.async.commit_group;");
        }

        for (int it = 0; it < ITERSU; ++it) {
            asm volatile("cp.async.wait_group %0;" :: "n"(STAGES - 2));
            __syncthreads();
            if (it + STAGES - 1 < ITERSU)
                issue_stage(sb, (it + STAGES - 1) % STAGES, it + STAGES - 1,
                            m0, n0, kb0, tid);
            asm volatile("cp.async.commit_group;");

            const int buf = it % STAGES;
            const uint32_t aBase = sb + buf * STAGE_BYTES
                                 + (uint32_t)((wm * 32 + arow) * SROW_H + acol) * 2;
            const uint32_t bBase = sb + buf * STAGE_BYTES + A_BYTES
                                 + (uint32_t)((wn * 32 + brow) * SROW_H + bcol) * 2;

#pragma unroll
            for (int kb = 0; kb < CHUNK; kb += 16) {
                uint32_t af[2][4], bf[4][2];
                LDSM4(af[0][0], af[0][1], af[0][2], af[0][3], aBase + kb * 2);
                LDSM4(af[1][0], af[1][1], af[1][2], af[1][3],
                      aBase + 16 * SROW_H * 2 + kb * 2);
                LDSM4(bf[0][0], bf[0][1], bf[1][0], bf[1][1], bBase + kb * 2);
                LDSM4(bf[2][0], bf[2][1], bf[3][0], bf[3][1],
                      bBase + 16 * SROW_H * 2 + kb * 2);
#pragma unroll
                for (int mi = 0; mi < 2; mi++)
#pragma unroll
                    for (int ni = 0; ni < 4; ni++) {
                        asm volatile(
                            "mma.sync.aligned.m16n8k16.row.col.f32.f16.f16.f32 "
                            "{%0,%1,%2,%3}, {%4,%5,%6,%7}, {%8,%9}, {%0,%1,%2,%3};"
                            : "+f"(acc[mi][ni][0]), "+f"(acc[mi][ni][1]),
                              "+f"(acc[mi][ni][2]), "+f"(acc[mi][ni][3])
                            : "r"(af[mi][0]), "r"(af[mi][1]),
                              "r"(af[mi][2]), "r"(af[mi][3]),
                              "r"(bf[ni][0]), "r"(bf[ni][1]));
                    }
            }
        }

        // Epilogue: write partial tile to g_part[ks]
        float* part = g_part + (size_t)ks * BROWS * OUTF;
#pragma unroll
        for (int mi = 0; mi < 2; mi++)
#pragma unroll
            for (int ni = 0; ni < 4; ni++) {
                int row = m0 + wm * 32 + mi * 16 + g;
                int col = n0 + wn * 32 + ni * 8 + 2 * t;
                float2 v0 = make_float2(acc[mi][ni][0], acc[mi][ni][1]);
                float2 v1 = make_float2(acc[mi][ni][2], acc[mi][ni][3]);
                *(float2*)&part[(size_t)row * OUTF + col]       = v0;
                *(float2*)&part[(size_t)(row + 8) * OUTF + col] = v1;
            }
        // next-unit top-of-loop barrier protects smem stage reuse
    }
}

// ---------------------------------------------------------------------------
// Kernel 4: reduce partials -> out
// ---------------------------------------------------------------------------
#define RED_N ((BROWS * OUTF) / 4)   // float4 count = 1048576
__global__ __launch_bounds__(256) void reduce_kernel(float* __restrict__ out) {
    int i = blockIdx.x * 256 + threadIdx.x;
    const float4* p = (const float4*)g_part;
    float4 a = p[i];
    float4 b = p[i + RED_N];
    float4 c = p[i + 2 * RED_N];
    float4 d = p[i + 3 * RED_N];
    float4 r;
    r.x = (a.x + b.x) + (c.x + d.x);
    r.y = (a.y + b.y) + (c.y + d.y);
    r.z = (a.z + b.z) + (c.z + d.z);
    r.w = (a.w + b.w) + (c.w + d.w);
    ((float4*)out)[i] = r;
}

// ---------------------------------------------------------------------------
extern "C" void kernel_launch(void* const* d_in, const int* in_sizes, int n_in,
                              void* d_out, int out_size) {
    const float* x    = (const float*)d_in[0];
    const float* bw   = (const float*)d_in[1];
    const float* sw   = (const float*)d_in[2];
    const float* grid = (const float*)d_in[3];
    float* out = (float*)d_out;

    cudaFuncSetAttribute(gemm_kernel, cudaFuncAttributeMaxDynamicSharedMemorySize,
                         SMEM_TOTAL);

    act_kernel<<<(BROWS * INF) / (256 * ACT_EPT), 256>>>(x, grid);
    wconv_kernel<<<(OUTF * INF) / 256, 256>>>(bw, sw);
    gemm_kernel<<<GCTAS, GTHREADS, SMEM_TOTAL>>>();
    reduce_kernel<<<RED_N / 256, 256>>>(out);
}

// round 13
// speedup vs baseline: 1.0595x; 1.0595x over previous
#include <cuda_runtime.h>
#include <cuda_fp16.h>
#include <cstdint>

#define BROWS 4096
#define INF   1024
#define OUTF  1024
#define KDIM  9216          // INF * 9  (silu + 8 basis columns per input feature)

// GEMM config (round-8 measured-best): persistent, 128x64 tiles, split-K=4
#define TMd 128
#define TNd 64
#define KSPLIT 4
#define KPER  (KDIM / KSPLIT)   // 2304
#define CHUNK 64                // k-chunk in halfs
#define ITERSU (KPER / CHUNK)   // 36
#define STAGES 3
#define SROW_H 72               // smem row stride in halfs (144 B, conflict-free)
#define A_BYTES (TMd * SROW_H * 2)        // 18432
#define B_BYTES (TNd * SROW_H * 2)        // 9216
#define STAGE_BYTES (A_BYTES + B_BYTES)   // 27648
#define SMEM_TOTAL (STAGES * STAGE_BYTES + 16)  // 82960
#define NUNITS ((BROWS / TMd) * (OUTF / TNd) * KSPLIT)  // 2048
#define GCTAS 296
#define GTHREADS 128

// Scratch (static device globals — no runtime allocation)
__device__ __align__(256) __half g_act[(size_t)BROWS * KDIM];   // 75 MB
__device__ __align__(256) __half g_w[(size_t)OUTF * KDIM];      // 19 MB
__device__ __align__(256) __half g_part[(size_t)KSPLIT * BROWS * OUTF];  // 33.5 MB
__device__ int g_ctr;

// ---------------------------------------------------------------------------
// Kernel 1 (merged prep, 18KB smem so occupancy is unhurt):
//  blocks [0, 4096): activation matrix — closed-form uniform cubic B-spline.
//  blocks [4096, 8192): weight interleave W[o, i*9+0]=bw, [..+1+q]=sw[o,i,q].
// ---------------------------------------------------------------------------
#define ACT_EPT 4
#define ACT_U4  ((256 * ACT_EPT * 9) / 8)              // 1152 uint4 per act block
#define ACT_BLOCKS ((BROWS * INF) / (256 * ACT_EPT))   // 4096
#define W_BLOCKS   ((OUTF * INF) / 256)                // 4096

__global__ __launch_bounds__(256) void prep_kernel(const float* __restrict__ x,
                                                   const float* __restrict__ grid,
                                                   const float* __restrict__ bw,
                                                   const float* __restrict__ sw) {
    __shared__ __half sbuf[256 * ACT_EPT * 9];   // 18432 B
    const int tid = threadIdx.x;
    const int bid = blockIdx.x;
    if (bid == 0 && tid == 0) g_ctr = 0;         // reset GEMM work queue

    if (bid < ACT_BLOCKS) {
        const size_t base = (size_t)bid * (256 * ACT_EPT);
        const float g0   = __ldg(grid);
        const float invh = 11.f / (__ldg(grid + 11) - g0);

        // zero-fill staging tile (1152 uint4, strided: 4.5 per thread)
        uint4 z; z.x = z.y = z.z = z.w = 0u;
        for (int i = tid; i < ACT_U4; i += 256)
            ((uint4*)sbuf)[i] = z;
        __syncthreads();

#pragma unroll
        for (int e = 0; e < ACT_EPT; e++) {
            const int loc = tid + e * 256;
            float xv = x[base + loc];

            float u = (xv - g0) * invh;
            float jf = floorf(u);
            int j = (int)jf;
            j = j < 0 ? 0 : (j > 10 ? 10 : j);
            float f = u - (float)j;
            float f2 = f * f, f3 = f2 * f;
            float om = 1.f - f;
            float p0 = f3 * (1.f / 6.f);                 // basis q = j
            float p3 = om * om * om * (1.f / 6.f);       // basis q = j-3
            float p2 = 0.5f * f3 - f2 + (4.f / 6.f);     // basis q = j-2
            float p1 = 1.f - p0 - p2 - p3;               // basis q = j-1

            float s = xv * __frcp_rn(1.f + __expf(-xv)); // silu

            __half* o = sbuf + loc * 9;
            o[0] = __float2half_rn(s);
            if (j < 8)               o[1 + j]     = __float2half_rn(p0);
            if (j >= 1 && j - 1 < 8) o[1 + j - 1] = __float2half_rn(p1);
            if (j >= 2 && j - 2 < 8) o[1 + j - 2] = __float2half_rn(p2);
            if (j >= 3 && j - 3 < 8) o[1 + j - 3] = __float2half_rn(p3);
        }
        __syncthreads();

        const uint4* s4 = (const uint4*)sbuf;            // 1152 x 16B
        uint4* g4 = (uint4*)(g_act + base * 9);
        for (int i = tid; i < ACT_U4; i += 256)
            g4[i] = s4[i];
    } else {
        const int wb = bid - ACT_BLOCKS;
        int idx = wb * 256 + tid;   // o*1024 + i
        __half* o = sbuf + tid * 9;
        o[0] = __float2half_rn(bw[idx]);
        const float4* sp = (const float4*)(sw + (size_t)idx * 8);
        float4 a = sp[0], b = sp[1];
        o[1] = __float2half_rn(a.x); o[2] = __float2half_rn(a.y);
        o[3] = __float2half_rn(a.z); o[4] = __float2half_rn(a.w);
        o[5] = __float2half_rn(b.x); o[6] = __float2half_rn(b.y);
        o[7] = __float2half_rn(b.z); o[8] = __float2half_rn(b.w);
        __syncthreads();

        const uint4* s4 = (const uint4*)sbuf;
        uint4* g4 = (uint4*)(g_w + (size_t)wb * 2304);
#pragma unroll
        for (int i = tid; i < 288; i += 256) g4[i] = s4[i];
    }
}

// ---------------------------------------------------------------------------
// Kernel 2: fp16 mma.sync GEMM, persistent split-K (round-8 config).
// 296 CTAs (2/SM), 2048 units, 4 warps (2m x 2n), warp tile 64x32.
// ---------------------------------------------------------------------------
__device__ __forceinline__ void issue_stage(uint32_t sb, int stage, int it,
                                            int m0, int n0, int kb0, int tid) {
    const int kk = kb0 + it * CHUNK;
    const uint32_t sA = sb + stage * STAGE_BYTES;
    const uint32_t sB = sA + A_BYTES;
#pragma unroll
    for (int j = 0; j < 12; j++) {            // 192 rows x 8 chunks = 1536 copies
        int id  = tid + j * GTHREADS;         // 0..1535
        int row = id >> 3, c = id & 7;
        if (row < TMd) {
            const __half* ga = &g_act[(size_t)(m0 + row) * KDIM + kk + c * 8];
            asm volatile("cp.async.cg.shared.global [%0], [%1], 16;"
                         :: "r"(sA + (uint32_t)(row * SROW_H + c * 8) * 2), "l"(ga));
        } else {
            int r2 = row - TMd;
            const __half* gb = &g_w[(size_t)(n0 + r2) * KDIM + kk + c * 8];
            asm volatile("cp.async.cg.shared.global [%0], [%1], 16;"
                         :: "r"(sB + (uint32_t)(r2 * SROW_H + c * 8) * 2), "l"(gb));
        }
    }
}

__global__ __launch_bounds__(GTHREADS, 2) void gemm_kernel() {
    extern __shared__ __align__(16) char smem[];
    const uint32_t sb = (uint32_t)__cvta_generic_to_shared(smem);
    int* s_unit = (int*)(smem + STAGES * STAGE_BYTES);
    const int tid = threadIdx.x;
    const int wid = tid >> 5, lane = tid & 31;
    const int g = lane >> 2, t = lane & 3;
    const int wm = wid >> 1, wn = wid & 1;     // 2 x 2 warp grid

    for (;;) {
        if (tid == 0) *s_unit = atomicAdd(&g_ctr, 1);
        __syncthreads();
        const int u = *s_unit;
        if (u >= NUNITS) break;
        const int m0  = (u >> 6) * TMd;         // 16 consecutive units share A strip
        const int ks  = (u >> 4) & 3;
        const int n0  = (u & 15) * TNd;
        const int kb0 = ks * KPER;

        float acc[4][4][4];
#pragma unroll
        for (int i = 0; i < 4; i++)
#pragma unroll
            for (int jj = 0; jj < 4; jj++)
#pragma unroll
                for (int r = 0; r < 4; r++) acc[i][jj][r] = 0.f;

#pragma unroll
        for (int s = 0; s < STAGES - 1; s++) {
            issue_stage(sb, s, s, m0, n0, kb0, tid);
            asm volatile("cp.async.commit_group;");
        }

        const int aRow = wm * 64 + g;
        const int bRow = wn * 32 + g;

        for (int it = 0; it < ITERSU; ++it) {
            asm volatile("cp.async.wait_group %0;" :: "n"(STAGES - 2));
            __syncthreads();
            if (it + STAGES - 1 < ITERSU)
                issue_stage(sb, (it + STAGES - 1) % STAGES, it + STAGES - 1,
                            m0, n0, kb0, tid);
            asm volatile("cp.async.commit_group;");

            const int buf = it % STAGES;
            const __half* As = (const __half*)(smem + buf * STAGE_BYTES);
            const __half* Bs = (const __half*)(smem + buf * STAGE_BYTES + A_BYTES);

#pragma unroll
            for (int kb = 0; kb < CHUNK; kb += 16) {
                uint32_t af[4][4], bf[4][2];
#pragma unroll
                for (int mi = 0; mi < 4; mi++) {
                    int r = aRow + mi * 16;
                    af[mi][0] = *(const uint32_t*)&As[r * SROW_H + kb + 2 * t];
                    af[mi][1] = *(const uint32_t*)&As[(r + 8) * SROW_H + kb + 2 * t];
                    af[mi][2] = *(const uint32_t*)&As[r * SROW_H + kb + 2 * t + 8];
                    af[mi][3] = *(const uint32_t*)&As[(r + 8) * SROW_H + kb + 2 * t + 8];
                }
#pragma unroll
                for (int ni = 0; ni < 4; ni++) {
                    int r = bRow + ni * 8;
                    bf[ni][0] = *(const uint32_t*)&Bs[r * SROW_H + kb + 2 * t];
                    bf[ni][1] = *(const uint32_t*)&Bs[r * SROW_H + kb + 2 * t + 8];
                }
#pragma unroll
                for (int mi = 0; mi < 4; mi++)
#pragma unroll
                    for (int ni = 0; ni < 4; ni++) {
                        asm volatile(
                            "mma.sync.aligned.m16n8k16.row.col.f32.f16.f16.f32 "
                            "{%0,%1,%2,%3}, {%4,%5,%6,%7}, {%8,%9}, {%0,%1,%2,%3};"
                            : "+f"(acc[mi][ni][0]), "+f"(acc[mi][ni][1]),
                              "+f"(acc[mi][ni][2]), "+f"(acc[mi][ni][3])
                            : "r"(af[mi][0]), "r"(af[mi][1]),
                              "r"(af[mi][2]), "r"(af[mi][3]),
                              "r"(bf[ni][0]), "r"(bf[ni][1]));
                    }
            }
        }

        // Epilogue: write fp16 partial tile to g_part[ks]
        __half* part = g_part + (size_t)ks * BROWS * OUTF;
#pragma unroll
        for (int mi = 0; mi < 4; mi++)
#pragma unroll
            for (int ni = 0; ni < 4; ni++) {
                int row = m0 + wm * 64 + mi * 16 + g;
                int col = n0 + wn * 32 + ni * 8 + 2 * t;
                __half2 h0 = __floats2half2_rn(acc[mi][ni][0], acc[mi][ni][1]);
                __half2 h1 = __floats2half2_rn(acc[mi][ni][2], acc[mi][ni][3]);
                *(__half2*)&part[(size_t)row * OUTF + col]       = h0;
                *(__half2*)&part[(size_t)(row + 8) * OUTF + col] = h1;
            }
        // next-unit top-of-loop barrier protects smem stage reuse
    }
}

// ---------------------------------------------------------------------------
// Kernel 3: reduce fp16 partials -> fp32 out (convert before summing)
// ---------------------------------------------------------------------------
#define PL_U4 ((BROWS * OUTF) / 8)   // uint4 (8 halfs) per plane = 524288
__global__ __launch_bounds__(256) void reduce_kernel(float* __restrict__ out) {
    int i = blockIdx.x * 256 + threadIdx.x;   // group of 8 output elems
    const uint4* p = (const uint4*)g_part;
    uint4 a = p[i], b = p[i + PL_U4], c = p[i + 2 * PL_U4], d = p[i + 3 * PL_U4];

    float4 r0, r1;
    {
        float2 fa = __half22float2(*(__half2*)&a.x), fb = __half22float2(*(__half2*)&b.x);
        float2 fc = __half22float2(*(__half2*)&c.x), fd = __half22float2(*(__half2*)&d.x);
        r0.x = (fa.x + fb.x) + (fc.x + fd.x);
        r0.y = (fa.y + fb.y) + (fc.y + fd.y);
    }
    {
        float2 fa = __half22float2(*(__half2*)&a.y), fb = __half22float2(*(__half2*)&b.y);
        float2 fc = __half22float2(*(__half2*)&c.y), fd = __half22float2(*(__half2*)&d.y);
        r0.z = (fa.x + fb.x) + (fc.x + fd.x);
        r0.w = (fa.y + fb.y) + (fc.y + fd.y);
    }
    {
        float2 fa = __half22float2(*(__half2*)&a.z), fb = __half22float2(*(__half2*)&b.z);
        float2 fc = __half22float2(*(__half2*)&c.z), fd = __half22float2(*(__half2*)&d.z);
        r1.x = (fa.x + fb.x) + (fc.x + fd.x);
        r1.y = (fa.y + fb.y) + (fc.y + fd.y);
    }
    {
        float2 fa = __half22float2(*(__half2*)&a.w), fb = __half22float2(*(__half2*)&b.w);
        float2 fc = __half22float2(*(__half2*)&c.w), fd = __half22float2(*(__half2*)&d.w);
        r1.z = (fa.x + fb.x) + (fc.x + fd.x);
        r1.w = (fa.y + fb.y) + (fc.y + fd.y);
    }
    ((float4*)out)[2 * i]     = r0;
    ((float4*)out)[2 * i + 1] = r1;
}

// ---------------------------------------------------------------------------
extern "C" void kernel_launch(void* const* d_in, const int* in_sizes, int n_in,
                              void* d_out, int out_size) {
    const float* x    = (const float*)d_in[0];
    const float* bw   = (const float*)d_in[1];
    const float* sw   = (const float*)d_in[2];
    const float* grid = (const float*)d_in[3];
    float* out = (float*)d_out;

    cudaFuncSetAttribute(gemm_kernel, cudaFuncAttributeMaxDynamicSharedMemorySize,
                         SMEM_TOTAL);

    prep_kernel<<<ACT_BLOCKS + W_BLOCKS, 256>>>(x, grid, bw, sw);
    gemm_kernel<<<GCTAS, GTHREADS, SMEM_TOTAL>>>();
    reduce_kernel<<<PL_U4 / 256, 256>>>(out);
}